// round 1
// baseline (speedup 1.0000x reference)
#include <cuda_runtime.h>

// Problem constants
#define B     256
#define NSRC  100
#define D     768
#define D4    192          // D / 4 (float4 units)
#define R     80
#define RP1   81

// Output layout (float element offsets), tuple order:
// vis_packed (B,R,D), txt_packed (B,R,D), text_mask (B,RP1),
// img_mask (B,RP1), rr_mod (B,R), labels (B,R)
#define VIS_OFF    0
#define TXT_OFF    (B*R*D)                       // 15,728,640
#define TMASK_OFF  (2*B*R*D)                     // 31,457,280
#define IMASK_OFF  (TMASK_OFF + B*RP1)           // 31,478,016
#define RRMOD_OFF  (IMASK_OFF + B*RP1)           // 31,498,752
#define LAB_OFF    (RRMOD_OFF + B*R)             // 31,519,232

#define TXT4_OFF   (TXT_OFF / 4)                 // float4 units

// dest-slot -> source-slot map; -1 means "write zeros"
__device__ int g_idx[B * R];

// One block per batch row: builds the stable compaction map + all small outputs.
__global__ void meta_kernel(const float* __restrict__ rrcp,
                            const float* __restrict__ labels_in,
                            float* __restrict__ out) {
    const int b = blockIdx.x;
    const int t = threadIdx.x;
    __shared__ float s_rr[R];
    __shared__ int s_count;

    if (t < R) {
        float rr = rrcp[b * NSRC + t];
        s_rr[t] = rr;
        // rr_mod = where(rr < 0.5, 0, rr)
        out[RRMOD_OFF + b * R + t] = (rr < 0.5f) ? 0.0f : rr;
        out[LAB_OFF + b * R + t]   = labels_in[b * NSRC + t];
    }
    __syncthreads();

    if (t == 0) {
        int count = 0;
        bool anynz = false;
        #pragma unroll 4
        for (int j = 0; j < R; ++j) {
            float rr = s_rr[j];
            if (rr > 0.5f) {                 // binary==1, stable order
                g_idx[b * R + count] = j;
                ++count;
            }
            if (rr >= 0.5f) anynz = true;    // rr_mod[j] != 0
        }
        for (int k = count; k < R; ++k) g_idx[b * R + k] = -1;
        if (!anynz) out[RRMOD_OFF + b * R + 0] = 1.0f;  // zero-row fix
        s_count = count;
    }
    __syncthreads();

    const int count = s_count;
    if (t < RP1) {
        float tm = (t <= count) ? 1.0f : 0.0f;
        out[TMASK_OFF + b * RP1 + t] = tm;
        out[IMASK_OFF + b * RP1 + t] = (b == B - 1) ? tm : 1.0f;
    }
}

// Bulk gather/pack: grid (R/4, B); each block handles 4 dest slots for
// both vis and txt (4 * 2 * 192 float4 = 24 KB moved per block).
__global__ void copy_kernel(const float4* __restrict__ vis,
                            const float4* __restrict__ txt,
                            float4* __restrict__ out) {
    const int b = blockIdx.y;
    const int base_slot = blockIdx.x * 4;
    __shared__ int s_idx[4];
    if (threadIdx.x < 4)
        s_idx[threadIdx.x] = g_idx[b * R + base_slot + threadIdx.x];
    __syncthreads();

    const float4 zero = make_float4(0.0f, 0.0f, 0.0f, 0.0f);
    #pragma unroll
    for (int q = threadIdx.x; q < 4 * 2 * D4; q += 256) {
        int t    = q % D4;
        int rest = q / D4;
        int half = rest & 1;    // 0 = vis, 1 = txt
        int r    = rest >> 1;   // which of 4 slots
        int src  = s_idx[r];
        const float4* __restrict__ srcp = half ? txt : vis;
        float4 v = zero;
        if (src >= 0)
            v = __ldg(&srcp[(b * NSRC + src) * D4 + t]);
        int dst = (half ? TXT4_OFF : 0) + (b * R + base_slot + r) * D4 + t;
        out[dst] = v;
    }
}

extern "C" void kernel_launch(void* const* d_in, const int* in_sizes, int n_in,
                              void* d_out, int out_size) {
    // Inputs per setup order:
    // 0: mean_pooling_vec (unused)  1: merge_text_vec (unused)
    // 2: vis (B,N,1,D)  3: txt (B,N,1,D)  4: labels (B,N)  5: RRCP (B,N)
    const float4* vis = (const float4*)d_in[2];
    const float4* txt = (const float4*)d_in[3];
    const float*  lab = (const float*)d_in[4];
    const float*  rr  = (const float*)d_in[5];
    float* out = (float*)d_out;

    meta_kernel<<<B, 128>>>(rr, lab, out);
    copy_kernel<<<dim3(R / 4, B), 256>>>(vis, txt, (float4*)out);
}

// round 4
// speedup vs baseline: 1.2321x; 1.2321x over previous
#include <cuda_runtime.h>

// Problem constants
#define B     256
#define NSRC  100
#define D4    192          // 768 / 4 (float4 units per embedding)
#define R     80
#define RP1   81

// Output layout (float element offsets), tuple order:
// vis_packed (B,R,768), txt_packed (B,R,768), text_mask (B,81),
// img_mask (B,81), rr_mod (B,80), labels (B,80)
#define TXT_OFF    (B*R*768)
#define TMASK_OFF  (2*B*R*768)
#define IMASK_OFF  (TMASK_OFF + B*RP1)
#define RRMOD_OFF  (IMASK_OFF + B*RP1)
#define LAB_OFF    (RRMOD_OFF + B*R)
#define TXT4_OFF   (TXT_OFF / 4)

#define SLOTS_PER_BLK 8

// Fused kernel: grid (R/8, B), 192 threads.
// Warp 0 rebuilds the stable compaction map for row b via ballots (cheap,
// rr row is L2-resident); then all threads stream 8 slots x {vis,txt}.
__global__ __launch_bounds__(192) void fused_kernel(
    const float4* __restrict__ vis,
    const float4* __restrict__ txt,
    const float*  __restrict__ labels_in,
    const float*  __restrict__ rrcp,
    float* __restrict__ out)
{
    const int b = blockIdx.y;
    const int t = threadIdx.x;

    __shared__ int s_map[R];    // dest slot -> src slot (-1 = zeros)
    __shared__ int s_count;

    if (t < 32) {
        // init map to -1 (80 entries, 3 rounds)
        #pragma unroll
        for (int c = 0; c < 3; ++c) {
            int j = c * 32 + t;
            if (j < R) s_map[j] = -1;
        }
        __syncwarp();

        const unsigned lt = (1u << t) - 1u;
        int base = 0;
        bool anynz = false;
        #pragma unroll
        for (int c = 0; c < 3; ++c) {
            int j = c * 32 + t;
            float rr = (j < R) ? rrcp[b * NSRC + j] : 0.0f;
            unsigned selm = __ballot_sync(0xFFFFFFFFu, (j < R) && (rr > 0.5f));
            if ((j < R) && (rr > 0.5f))
                s_map[base + __popc(selm & lt)] = j;
            anynz |= (j < R) && (rr >= 0.5f);
            base += __popc(selm);
        }
        anynz = __ballot_sync(0xFFFFFFFFu, anynz) != 0u;
        if (t == 0) {
            s_count = base;
            // rr_mod zero-row fix owned by the x==0 block of this row
            if (blockIdx.x == 0 && !anynz)
                out[RRMOD_OFF + b * R + 0] = 1.0f;
        }
    }
    __syncthreads();

    // Small per-row outputs (one block per row does them)
    if (blockIdx.x == 0) {
        const int count = s_count;
        if (t < R) {
            float rr = rrcp[b * NSRC + t];
            float rm = (rr < 0.5f) ? 0.0f : rr;
            if (t == 0 && count == 0) {
                // preserve the fix written above when the whole row is zero;
                // recompute anynz cheaply: row has no rr>=0.5 iff fix applied.
                // (covered by the warp-0 write; only write rm when it won't clobber)
                bool rowzero = true;
                #pragma unroll 4
                for (int j = 0; j < R; ++j)
                    rowzero &= (rrcp[b * NSRC + j] < 0.5f);
                if (!rowzero) out[RRMOD_OFF + b * R] = rm;
            } else {
                out[RRMOD_OFF + b * R + t] = rm;
            }
            out[LAB_OFF + b * R + t] = labels_in[b * NSRC + t];
        }
        if (t < RP1) {
            float tm = (t <= count) ? 1.0f : 0.0f;
            out[TMASK_OFF + b * RP1 + t] = tm;
            out[IMASK_OFF + b * RP1 + t] = (b == B - 1) ? tm : 1.0f;
        }
    }

    // Bulk gather: 8 slots, both halves, column = t. No div/mod.
    const int slot0 = blockIdx.x * SLOTS_PER_BLK;
    const float4 zero = make_float4(0.0f, 0.0f, 0.0f, 0.0f);
    const float4* __restrict__ vbase = vis + (size_t)b * NSRC * D4 + t;
    const float4* __restrict__ tbase = txt + (size_t)b * NSRC * D4 + t;
    float4* __restrict__ ov = (float4*)out + (size_t)(b * R + slot0) * D4 + t;
    float4* __restrict__ ot = (float4*)out + TXT4_OFF + (size_t)(b * R + slot0) * D4 + t;

    #pragma unroll
    for (int g = 0; g < SLOTS_PER_BLK / 4; ++g) {
        const int s0 = s_map[slot0 + g * 4 + 0];
        const int s1 = s_map[slot0 + g * 4 + 1];
        const int s2 = s_map[slot0 + g * 4 + 2];
        const int s3 = s_map[slot0 + g * 4 + 3];
        // front-batch 8 independent loads
        float4 v0 = (s0 >= 0) ? __ldg(vbase + s0 * D4) : zero;
        float4 v1 = (s1 >= 0) ? __ldg(vbase + s1 * D4) : zero;
        float4 v2 = (s2 >= 0) ? __ldg(vbase + s2 * D4) : zero;
        float4 v3 = (s3 >= 0) ? __ldg(vbase + s3 * D4) : zero;
        float4 x0 = (s0 >= 0) ? __ldg(tbase + s0 * D4) : zero;
        float4 x1 = (s1 >= 0) ? __ldg(tbase + s1 * D4) : zero;
        float4 x2 = (s2 >= 0) ? __ldg(tbase + s2 * D4) : zero;
        float4 x3 = (s3 >= 0) ? __ldg(tbase + s3 * D4) : zero;
        ov[(g * 4 + 0) * D4] = v0;
        ov[(g * 4 + 1) * D4] = v1;
        ov[(g * 4 + 2) * D4] = v2;
        ov[(g * 4 + 3) * D4] = v3;
        ot[(g * 4 + 0) * D4] = x0;
        ot[(g * 4 + 1) * D4] = x1;
        ot[(g * 4 + 2) * D4] = x2;
        ot[(g * 4 + 3) * D4] = x3;
    }
}

extern "C" void kernel_launch(void* const* d_in, const int* in_sizes, int n_in,
                              void* d_out, int out_size) {
    // 0: mean_pooling_vec (unused)  1: merge_text_vec (unused)
    // 2: vis (B,N,1,D)  3: txt (B,N,1,D)  4: labels (B,N)  5: RRCP (B,N)
    const float4* vis = (const float4*)d_in[2];
    const float4* txt = (const float4*)d_in[3];
    const float*  lab = (const float*)d_in[4];
    const float*  rr  = (const float*)d_in[5];
    float* out = (float*)d_out;

    fused_kernel<<<dim3(R / SLOTS_PER_BLK, B), 192>>>(vis, txt, lab, rr, out);
}